// round 11
// baseline (speedup 1.0000x reference)
#include <cuda_runtime.h>
#include <cuda_bf16.h>
#include <math.h>
#include <stdint.h>

// Problem constants
#define Bn  32
#define Cc  80
#define TXn 512
#define TYn 2048
#define K2  160          // stacked K: [scale(80); mean*scale(80)]
#define NEGV (-1e9f)
#define LOG2PI 1.8378770664093453f

// Output layout (flat f32, reference return order)
#define Z_OFF        0
#define YMEAN_OFF    (Bn*Cc*TYn)
#define YLOG_OFF     (2*Bn*Cc*TYn)
#define ATTN_OFF     (3*Bn*Cc*TYn)
#define ODUR_OFF     (ATTN_OFF + Bn*TYn*TXn)
#define OADUR_OFF    (ODUR_OFF + Bn*TXn)

// -------------------- scratch (__device__ globals) --------------------------
__device__ float    g_W[Bn*K2*TXn];              // [b][k][x]
__device__ float    g_Z[Bn*K2*TYn];              // [b][k][y]
__device__ float    g_rowA[Bn*TXn];              // logp1+logp4 per (b,x)
__device__ float    g_logpT[(size_t)Bn*TYn*TXn]; // 134 MB [b][y][x]
// dir bits: word per (thread t, 8-col block): bit ((j&7)*4 + (x&3)),
// word index = (b*(TYn/8) + (j>>3))*128 + (x>>2). 4 MB.
__device__ unsigned g_dbits[(size_t)Bn*(TYn/8)*128];
__device__ int      g_xy[Bn*TYn];                // alignment index per (b,y)
__device__ int      g_cnt[Bn*TXn];               // per-x duration counts

// -------------------- K1: per-(b,x) prep -------------------------------------
__global__ void prepx_kernel(const float* __restrict__ om,
                             const float* __restrict__ ols,
                             const float* __restrict__ odur,
                             float* __restrict__ out)
{
    int i = blockIdx.x * blockDim.x + threadIdx.x;
    if (i >= Bn*TXn) return;
    int b = i / TXn, x = i % TXn;
    const float* omb = om  + (size_t)b*Cc*TXn + x;
    const float* olb = ols + (size_t)b*Cc*TXn + x;
    float* wS = g_W + (size_t)b*K2*TXn + x;
    float sa = 0.f;
    #pragma unroll 4
    for (int c = 0; c < Cc; c++) {
        float l  = olb[(size_t)c*TXn];
        float sc = expf(-2.f*l);
        float m  = omb[(size_t)c*TXn];
        wS[(size_t)c*TXn]        = sc;
        wS[(size_t)(Cc+c)*TXn]   = m*sc;
        sa += -0.5f*LOG2PI - l - 0.5f*m*m*sc;
    }
    g_rowA[i] = sa;
    g_cnt[i]  = 0;
    out[ODUR_OFF + i] = odur[i];
}

// -------------------- K2: z masking + Z matrix --------------------------------
__global__ void prepz_kernel(const float* __restrict__ z,
                             const int* __restrict__ yl,
                             float* __restrict__ out)
{
    int i = blockIdx.x * blockDim.x + threadIdx.x;
    if (i >= Bn*Cc*TYn) return;
    int b = i / (Cc*TYn);
    int r = i % (Cc*TYn);
    int c = r / TYn;
    int y = r % TYn;
    float zv = z[i];
    if (y >= yl[b]) zv = 0.f;
    out[Z_OFF + i] = zv;
    size_t zb = (size_t)b*K2*TYn;
    g_Z[zb + (size_t)c*TYn + y]      = -0.5f*zv*zv;
    g_Z[zb + (size_t)(Cc+c)*TYn + y] = zv;
}

// -------------------- K3: logp GEMM (128x128 tile, band-pruned) ---------------
__global__ void __launch_bounds__(256, 2)
gemm_kernel(const int* __restrict__ xl, const int* __restrict__ yl)
{
    int b  = blockIdx.z;
    int x0 = blockIdx.x * 128;
    int y0 = blockIdx.y * 128;
    int xlen = xl[b], ylen = yl[b];
    if (x0 >= xlen || y0 >= ylen) return;
    if (x0 > y0 + 127) return;                      // entirely above diagonal (x>j)
    if (x0 + 127 < y0 - (ylen - xlen)) return;      // entirely below reachable band

    __shared__ float zs[16][128];   // k x y
    __shared__ float ws[16][128];   // k x x

    int tid  = threadIdx.x;
    int lrow = tid >> 4;            // 0..15
    int lcol = (tid & 15) << 3;     // 0..120
    int ty   = tid >> 4;            // 0..15
    int tx   = tid & 15;            // 0..15

    const float* Zb = g_Z + (size_t)b*K2*TYn;
    const float* Wb = g_W + (size_t)b*K2*TXn;

    float acc[8][8] = {};

    for (int k0 = 0; k0 < K2; k0 += 16) {
        const float* zp = Zb + (size_t)(k0+lrow)*TYn + y0 + lcol;
        const float* wp = Wb + (size_t)(k0+lrow)*TXn + x0 + lcol;
        *(float4*)&zs[lrow][lcol]   = *(const float4*)zp;
        *(float4*)&zs[lrow][lcol+4] = *(const float4*)(zp+4);
        *(float4*)&ws[lrow][lcol]   = *(const float4*)wp;
        *(float4*)&ws[lrow][lcol+4] = *(const float4*)(wp+4);
        __syncthreads();
        #pragma unroll
        for (int k = 0; k < 16; k++) {
            float4 z0 = *(float4*)&zs[k][ty<<3];
            float4 z1 = *(float4*)&zs[k][(ty<<3)+4];
            float4 w0 = *(float4*)&ws[k][tx<<3];
            float4 w1 = *(float4*)&ws[k][(tx<<3)+4];
            float za[8] = {z0.x,z0.y,z0.z,z0.w,z1.x,z1.y,z1.z,z1.w};
            float wa[8] = {w0.x,w0.y,w0.z,w0.w,w1.x,w1.y,w1.z,w1.w};
            #pragma unroll
            for (int i = 0; i < 8; i++)
                #pragma unroll
                for (int j = 0; j < 8; j++)
                    acc[i][j] += za[i]*wa[j];
        }
        __syncthreads();
    }

    float ra[8];
    #pragma unroll
    for (int j = 0; j < 8; j++)
        ra[j] = g_rowA[b*TXn + x0 + (tx<<3) + j];

    #pragma unroll
    for (int i = 0; i < 8; i++) {
        int y = y0 + (ty<<3) + i;
        float* op = g_logpT + ((size_t)b*TYn + y)*TXn + x0 + (tx<<3);
        float4 o0, o1;
        float* p0 = (float*)&o0; float* p1 = (float*)&o1;
        bool yok = (y < ylen);
        #pragma unroll
        for (int j = 0; j < 4; j++) {
            int xa = x0 + (tx<<3) + j;
            int xb = xa + 4;
            p0[j] = (yok && xa < xlen) ? (acc[i][j]   + ra[j])   : 0.f;
            p1[j] = (yok && xb < xlen) ? (acc[i][j+4] + ra[j+4]) : 0.f;
        }
        *(float4*)op       = o0;
        *(float4*)(op + 4) = o1;
    }
}

// -------------------- K4: forward Viterbi (in-register halo) -------------------
// 128 threads; thread t owns x=4t..4t+3 (v0..v3) plus an in-register halo copy
// of thread t-1's range (h0..h3). For 4 columns all dependencies are
// same-thread registers (v0's left = h3; halo advances with h[-1]=NEG, and
// h3 stays exact for 4 columns). Exchange (shfl + smem + one barrier) every
// 4 columns only.
__global__ void __launch_bounds__(128)
fwd_kernel(const int* __restrict__ xl, const int* __restrict__ yl)
{
    int b = blockIdx.x, t = threadIdx.x;
    int w = t >> 5, lane = t & 31;
    int xlen = xl[b], ylen = yl[b];
    int x0 = t << 2;

    __shared__ float4 sb[2][4];       // [parity][warp] lane31 boundary

    unsigned fmask = 0u;              // force-stay bits for x >= xlen
    #pragma unroll
    for (int i = 0; i < 4; i++)
        if (x0 + i >= xlen) fmask |= (0x11111111u << i);

    float v0=0.f, v1=0.f, v2=0.f, v3=0.f;
    float h0=NEGV, h1=NEGV, h2=NEGV, h3=NEGV;

    const float4* basev = (const float4*)(g_logpT + (size_t)b*TYn*TXn) + t;
    const float4* baseh = (t == 0) ? basev : (basev - 1);   // x0-4 (dummy for t==0)
    const int str4 = TXn / 4;

    unsigned* db = g_dbits + (size_t)b*(TYn/8)*128 + t;

    float4 co[2][4], ch[2][4];        // prefetch: phase-parity buffers
    #pragma unroll
    for (int d = 0; d < 8; d++) {
        bool ok = d < ylen;
        co[d>>2][d&3] = ok ? basev[(size_t)d*str4] : make_float4(0,0,0,0);
        ch[d>>2][d&3] = ok ? baseh[(size_t)d*str4] : make_float4(0,0,0,0);
    }

    unsigned bits = 0u;

    auto phase = [&](int j0, bool ramp) {
        int pp = (j0 >> 2) & 1;
        // boundary exchange: h <- left thread's v (exact copy)
        if (lane == 31) sb[pp][w] = make_float4(v0, v1, v2, v3);
        __syncthreads();
        {
            float4 hb = (w > 0) ? sb[pp][w-1]
                                : make_float4(NEGV, NEGV, NEGV, NEGV);
            float s0 = __shfl_up_sync(0xFFFFFFFFu, v0, 1);
            float s1 = __shfl_up_sync(0xFFFFFFFFu, v1, 1);
            float s2 = __shfl_up_sync(0xFFFFFFFFu, v2, 1);
            float s3 = __shfl_up_sync(0xFFFFFFFFu, v3, 1);
            h0 = (lane == 0) ? hb.x : s0;
            h1 = (lane == 0) ? hb.y : s1;
            h2 = (lane == 0) ? hb.z : s2;
            h3 = (lane == 0) ? hb.w : s3;
        }
        #pragma unroll
        for (int d = 0; d < 4; d++) {
            int j = j0 + d;
            if (j < ylen) {                       // block-uniform
                float4 cv = co[pp][d];
                float4 cc = ch[pp][d];
                int jp = j + 8;
                bool pok = (jp < ylen);
                co[pp][d] = pok ? basev[(size_t)jp*str4] : make_float4(0,0,0,0);
                ch[pp][d] = pok ? baseh[(size_t)jp*str4] : make_float4(0,0,0,0);

                // halo advance (h[-1] = NEG)
                float nh0 = h0 + cc.x;
                float nh1 = fmaxf(h1, h0) + cc.y;
                float nh2 = fmaxf(h2, h1) + cc.z;
                float nh3 = fmaxf(h3, h2) + cc.w;
                // owner update + dir bits (old v, old h3)
                bool  b0 = v0 >= h3;
                bool  b1 = v1 >= v0;
                bool  b2 = v2 >= v1;
                bool  b3 = v3 >= v2;
                float nv0 = fmaxf(v0, h3) + cv.x;
                float nv1 = fmaxf(v1, v0) + cv.y;
                float nv2 = fmaxf(v2, v1) + cv.z;
                float nv3 = fmaxf(v3, v2) + cv.w;
                if (ramp) {
                    if (x0     > j) nv0 = NEGV;
                    if (x0 + 1 > j) nv1 = NEGV;
                    if (x0 + 2 > j) nv2 = NEGV;
                    if (x0 + 3 > j) nv3 = NEGV;
                    int xh = x0 - 4;
                    if (xh     > j) nh0 = NEGV;
                    if (xh + 1 > j) nh1 = NEGV;
                    if (xh + 2 > j) nh2 = NEGV;
                    if (xh + 3 > j) nh3 = NEGV;
                }
                unsigned nib = (b0?1u:0u) | (b1?2u:0u) | (b2?4u:0u) | (b3?8u:0u);
                bits |= nib << ((j & 7) << 2);
                v0=nv0; v1=nv1; v2=nv2; v3=nv3;
                h0=nh0; h1=nh1; h2=nh2; h3=nh3;
            }
        }
        bool last = (j0 + 4 >= ylen);
        if ((j0 & 4) == 4 || last) {
            db[(size_t)(j0 >> 3) * 128] = bits | fmask;
            bits = 0u;
        }
    };

    int ramp_end = (512 < ylen) ? 512 : ylen;
    int j0 = 0;
    for (; j0 < ramp_end; j0 += 4) phase(j0, true);
    for (; j0 < ylen;     j0 += 4) phase(j0, false);
}

// -------------------- K5: backtrack + count (1 thread walks, prefetched) -------
// bit(x,j) = g_dbits[(b*(TYn/8) + (j>>3))*128 + (x>>2)] >> ((j&7)*4 + (x&3)).
// Per 8-col block the walk needs words (idx>>2)-{0..4}; prefetch the next
// block's 5 candidates while walking the current one.
__global__ void __launch_bounds__(32)
bwd_kernel(const int* __restrict__ xl, const int* __restrict__ yl)
{
    int b = blockIdx.x, lane = threadIdx.x;
    int xlen = xl[b], ylen = yl[b];

    for (int j = ylen + lane; j < TYn; j += 32) g_xy[b*TYn + j] = 0;
    __syncwarp();
    if (lane != 0) return;

    const unsigned* D = g_dbits + (size_t)b*(TYn/8)*128;
    int idx = xlen - 1;
    int jb  = (ylen - 1) >> 3;

    int w0 = idx >> 2;
    unsigned P0, P1, P2, P3, P4;
    P0 = D[(size_t)jb*128 + w0];
    P1 = (w0 >= 1) ? D[(size_t)jb*128 + w0 - 1] : 0xFFFFFFFFu;
    P2 = (w0 >= 2) ? D[(size_t)jb*128 + w0 - 2] : 0xFFFFFFFFu;
    P3 = (w0 >= 3) ? D[(size_t)jb*128 + w0 - 3] : 0xFFFFFFFFu;
    P4 = (w0 >= 4) ? D[(size_t)jb*128 + w0 - 4] : 0xFFFFFFFFu;

    for (; jb >= 0; jb--) {
        int kmax = ylen - 1 - (jb << 3);
        if (kmax > 7) kmax = 7;

        // prefetch next block using current idx as anchor
        unsigned N0=0xFFFFFFFFu, N1=0xFFFFFFFFu, N2=0xFFFFFFFFu,
                 N3=0xFFFFFFFFu, N4=0xFFFFFFFFu;
        int wn = idx >> 2;
        if (jb > 0) {
            const unsigned* Dn = D + (size_t)(jb-1)*128;
            N0 = Dn[wn];
            N1 = (wn >= 1) ? Dn[wn - 1] : 0xFFFFFFFFu;
            N2 = (wn >= 2) ? Dn[wn - 2] : 0xFFFFFFFFu;
            N3 = (wn >= 3) ? Dn[wn - 3] : 0xFFFFFFFFu;
            N4 = (wn >= 4) ? Dn[wn - 4] : 0xFFFFFFFFu;
        }

        for (int k = kmax; k >= 0; k--) {
            int j = (jb << 3) + k;
            int off = w0 - (idx >> 2);        // 0..4
            unsigned word = (off == 0) ? P0 : (off == 1) ? P1 :
                            (off == 2) ? P2 : (off == 3) ? P3 : P4;
            g_xy[b*TYn + j] = idx;
            atomicAdd(&g_cnt[b*TXn + idx], 1);
            unsigned bit = (word >> ((k << 2) + (idx & 3))) & 1u;
            idx += (int)bit - 1;
        }
        P0 = N0; P1 = N1; P2 = N2; P3 = N3; P4 = N4;
        w0 = wn;
    }
}

// -------------------- K6: y_mean / y_log_scale gathers -------------------------
__global__ void gather_kernel(const float* __restrict__ om,
                              const float* __restrict__ ols,
                              const int* __restrict__ yl,
                              float* __restrict__ out)
{
    int i = blockIdx.x * blockDim.x + threadIdx.x;
    if (i >= Bn*Cc*TYn) return;
    int b = i / (Cc*TYn);
    int r = i % (Cc*TYn);
    int c = r / TYn;
    int y = r % TYn;
    float m = 0.f, s = 0.f;
    if (y < yl[b]) {
        int x = g_xy[b*TYn + y];
        m = om [(size_t)(b*Cc + c)*TXn + x];
        s = ols[(size_t)(b*Cc + c)*TXn + x];
    }
    out[YMEAN_OFF + i] = m;
    out[YLOG_OFF  + i] = s;
}

// -------------------- K7: attn_out (zero + one-hot scatter) --------------------
__global__ void attn_kernel(const int* __restrict__ yl, float* __restrict__ out)
{
    int y = blockIdx.x, b = blockIdx.y, t = threadIdx.x;
    int xi = (y < yl[b]) ? g_xy[b*TYn + y] : -1;
    int x4 = t << 2;
    float4 r = make_float4(0.f, 0.f, 0.f, 0.f);
    if (xi >= x4 && xi < x4 + 4) ((float*)&r)[xi - x4] = 1.0f;
    *(float4*)&out[ATTN_OFF + ((size_t)b*TYn + y)*TXn + x4] = r;
}

// -------------------- K8: o_attn_dur --------------------------------------------
__global__ void dur_kernel(const int* __restrict__ xl, float* __restrict__ out)
{
    int i = blockIdx.x * blockDim.x + threadIdx.x;
    if (i >= Bn*TXn) return;
    int b = i / TXn, x = i % TXn;
    out[OADUR_OFF + i] = (x < xl[b]) ? log1pf((float)g_cnt[i]) : 0.f;
}

// -------------------- launch (single stream) -------------------------------------
extern "C" void kernel_launch(void* const* d_in, const int* in_sizes, int n_in,
                              void* d_out, int out_size)
{
    const float* om   = (const float*)d_in[0];
    const float* ols  = (const float*)d_in[1];
    const float* odur = (const float*)d_in[2];
    const float* z    = (const float*)d_in[3];
    const int*   xlen = (const int*)  d_in[4];
    const int*   ylen = (const int*)  d_in[5];
    float* out = (float*)d_out;

    prepx_kernel<<<(Bn*TXn + 255)/256, 256>>>(om, ols, odur, out);
    prepz_kernel<<<(Bn*Cc*TYn + 255)/256, 256>>>(z, ylen, out);
    gemm_kernel<<<dim3(TXn/128, TYn/128, Bn), 256>>>(xlen, ylen);
    fwd_kernel<<<Bn, 128>>>(xlen, ylen);
    bwd_kernel<<<Bn, 32>>>(xlen, ylen);
    gather_kernel<<<(Bn*Cc*TYn + 255)/256, 256>>>(om, ols, ylen, out);
    attn_kernel<<<dim3(TYn, Bn), 128>>>(ylen, out);
    dur_kernel<<<(Bn*TXn + 255)/256, 256>>>(xlen, out);
}

// round 12
// speedup vs baseline: 2.2767x; 2.2767x over previous
#include <cuda_runtime.h>
#include <cuda_bf16.h>
#include <math.h>
#include <stdint.h>

// Problem constants
#define Bn  32
#define Cc  80
#define TXn 512
#define TYn 2048
#define K2  160          // stacked K: [scale(80); mean*scale(80)]
#define NEGV (-1e9f)
#define LOG2PI 1.8378770664093453f
#define NYT (TYn/128)    // 16 y-tiles of 128 columns

// Output layout (flat f32, reference return order)
#define Z_OFF        0
#define YMEAN_OFF    (Bn*Cc*TYn)
#define YLOG_OFF     (2*Bn*Cc*TYn)
#define ATTN_OFF     (3*Bn*Cc*TYn)
#define ODUR_OFF     (ATTN_OFF + Bn*TYn*TXn)
#define OADUR_OFF    (ODUR_OFF + Bn*TXn)

// -------------------- scratch (__device__ globals) --------------------------
__device__ float    g_W[Bn*K2*TXn];              // [b][k][x]
__device__ float    g_Z[Bn*K2*TYn];              // [b][k][y]
__device__ float    g_rowA[Bn*TXn];              // logp1+logp4 per (b,x)
__device__ float    g_logpT[(size_t)Bn*TYn*TXn]; // 134 MB [b][y][x]
__device__ unsigned g_dbits[(size_t)Bn*TYn*16];  // dir bits, 32 per warp-word
__device__ int      g_xy[Bn*TYn];                // alignment index per (b,y)
__device__ int      g_cnt[Bn*TXn];               // per-x duration counts
__device__ int      g_prog[Bn*NYT];              // gemm tiles done per (b,ytile)

// -------------------- K1: per-(b,x) prep -------------------------------------
__global__ void prepx_kernel(const float* __restrict__ om,
                             const float* __restrict__ ols,
                             const float* __restrict__ odur,
                             float* __restrict__ out)
{
    int i = blockIdx.x * blockDim.x + threadIdx.x;
    if (i >= Bn*TXn) return;
    if (i < Bn*NYT) g_prog[i] = 0;     // reset producer counters each launch
    int b = i / TXn, x = i % TXn;
    const float* omb = om  + (size_t)b*Cc*TXn + x;
    const float* olb = ols + (size_t)b*Cc*TXn + x;
    float* wS = g_W + (size_t)b*K2*TXn + x;
    float sa = 0.f;
    #pragma unroll 4
    for (int c = 0; c < Cc; c++) {
        float l  = olb[(size_t)c*TXn];
        float sc = expf(-2.f*l);
        float m  = omb[(size_t)c*TXn];
        wS[(size_t)c*TXn]        = sc;
        wS[(size_t)(Cc+c)*TXn]   = m*sc;
        sa += -0.5f*LOG2PI - l - 0.5f*m*m*sc;
    }
    g_rowA[i] = sa;
    g_cnt[i]  = 0;
    out[ODUR_OFF + i] = odur[i];
}

// -------------------- K2: z masking + Z matrix --------------------------------
__global__ void prepz_kernel(const float* __restrict__ z,
                             const int* __restrict__ yl,
                             float* __restrict__ out)
{
    int i = blockIdx.x * blockDim.x + threadIdx.x;
    if (i >= Bn*Cc*TYn) return;
    int b = i / (Cc*TYn);
    int r = i % (Cc*TYn);
    int c = r / TYn;
    int y = r % TYn;
    float zv = z[i];
    if (y >= yl[b]) zv = 0.f;
    out[Z_OFF + i] = zv;
    size_t zb = (size_t)b*K2*TYn;
    g_Z[zb + (size_t)c*TYn + y]      = -0.5f*zv*zv;
    g_Z[zb + (size_t)(Cc+c)*TYn + y] = zv;
}

// -------------------- K3: fused gemm (producers) + forward DP (consumers) ------
// Blocks 0..31: forward Viterbi for batch b (verbatim R3 structure), gated per
// 128-column chunk on g_prog. Blocks 32..: one 128x128 logp tile each, ordered
// ytile-major so early columns complete first. Producers never wait ->
// deadlock-free; consumer scheduling delay only costs overlap, not correctness.
__global__ void __launch_bounds__(512)
fused_kernel(const int* __restrict__ xl, const int* __restrict__ yl)
{
    __shared__ float smem[2*16*128];       // gemm tiles (fwd uses tiny slice)
    int tid = threadIdx.x;

    if (blockIdx.x >= 32) {
        // ---------------- GEMM producer role ----------------
        int gid = blockIdx.x - 32;
        int yt  = gid >> 7;                // 0..15 (slab-major)
        int rem = gid & 127;
        int b   = rem >> 2;
        int x0  = (rem & 3) * 128;
        int y0  = yt * 128;
        int xlen = xl[b], ylen = yl[b];

        bool skip = (x0 >= xlen) || (y0 >= ylen) ||
                    (x0 > y0 + 127) || (x0 + 127 < y0 - (ylen - xlen));
        if (!skip) {
            float (*zs)[128] = (float (*)[128])smem;
            float (*ws)[128] = (float (*)[128])(smem + 16*128);
            int lrow = tid >> 5;           // 0..15
            int lcol = (tid & 31) << 2;    // 0..124
            int ty   = tid >> 4;           // 0..31 (4 y each)
            int tx   = tid & 15;           // 0..15 (8 x each)

            const float* Zb = g_Z + (size_t)b*K2*TYn;
            const float* Wb = g_W + (size_t)b*K2*TXn;

            float acc[4][8] = {};
            for (int k0 = 0; k0 < K2; k0 += 16) {
                *(float4*)&zs[lrow][lcol] =
                    *(const float4*)&Zb[(size_t)(k0+lrow)*TYn + y0 + lcol];
                *(float4*)&ws[lrow][lcol] =
                    *(const float4*)&Wb[(size_t)(k0+lrow)*TXn + x0 + lcol];
                __syncthreads();
                #pragma unroll
                for (int k = 0; k < 16; k++) {
                    float4 zf = *(float4*)&zs[k][ty<<2];
                    float4 w0 = *(float4*)&ws[k][tx<<3];
                    float4 w1 = *(float4*)&ws[k][(tx<<3)+4];
                    float za[4] = {zf.x, zf.y, zf.z, zf.w};
                    float wa[8] = {w0.x,w0.y,w0.z,w0.w,w1.x,w1.y,w1.z,w1.w};
                    #pragma unroll
                    for (int i = 0; i < 4; i++)
                        #pragma unroll
                        for (int j = 0; j < 8; j++)
                            acc[i][j] += za[i]*wa[j];
                }
                __syncthreads();
            }

            float ra[8];
            #pragma unroll
            for (int j = 0; j < 8; j++)
                ra[j] = g_rowA[b*TXn + x0 + (tx<<3) + j];

            #pragma unroll
            for (int i = 0; i < 4; i++) {
                int y = y0 + (ty<<2) + i;
                float* op = g_logpT + ((size_t)b*TYn + y)*TXn + x0 + (tx<<3);
                float4 o0, o1;
                float* p0 = (float*)&o0; float* p1 = (float*)&o1;
                bool yok = (y < ylen);
                #pragma unroll
                for (int j = 0; j < 4; j++) {
                    int xa = x0 + (tx<<3) + j;
                    int xb = xa + 4;
                    p0[j] = (yok && xa < xlen) ? (acc[i][j]   + ra[j])   : 0.f;
                    p1[j] = (yok && xb < xlen) ? (acc[i][j+4] + ra[j+4]) : 0.f;
                }
                *(float4*)op       = o0;
                *(float4*)(op + 4) = o1;
            }
        }
        // signal: writes -> per-thread fence -> barrier -> tid0 atomic
        __threadfence();
        __syncthreads();
        if (tid == 0) atomicAdd(&g_prog[b*NYT + yt], 1);
        return;
    }

    // ---------------- forward-DP consumer role (R3 body + gating) ----------------
    int b    = blockIdx.x;
    int x    = tid;
    int w    = x >> 5, lane = x & 31;
    int xlen = xl[b], ylen = yl[b];

    float* sb = smem;                     // [2][16] boundary values

    unsigned force;
    {
        int rel = xlen - (w << 5);
        if (rel <= 0)      force = 0xFFFFFFFFu;
        else if (rel < 32) force = 0xFFFFFFFFu << rel;
        else               force = 0u;
    }

    float v = 0.f;
    if (lane == 31) { sb[0*16 + w] = 0.f; sb[1*16 + w] = 0.f; }

    const float* base  = g_logpT + (size_t)b*TYn*TXn + x;
    unsigned*    dbase = g_dbits + (size_t)b*TYn*16 + w;

    int last_yt = (ylen - 1) >> 7;

    // gate helper: wait until all 4 x-tiles of (b, yt) are written
    auto gate = [&](int yt) {
        if (yt > last_yt) yt = last_yt;
        if (tid == 0) {
            const int* p = &g_prog[b*NYT + yt];
            int pv;
            do {
                asm volatile("ld.acquire.gpu.s32 %0, [%1];"
                             : "=r"(pv) : "l"(p) : "memory");
                if (pv < 4) __nanosleep(256);
            } while (pv < 4);
        }
        __syncthreads();
    };

    gate(0);                              // columns 0..15 (preload + first blocks)

    const int PF = 8;
    float c[PF];
    #pragma unroll
    for (int d = 0; d < PF; d++)
        c[d] = (d < ylen) ? base[(size_t)d*TXn] : 0.f;
    __syncthreads();

    for (int j0 = 0; j0 < ylen; j0 += PF) {
        // prefetch inside this block reaches j0+15; gate next chunk at 120 mod 128
        if ((j0 & 127) == 120) gate((j0 >> 7) + 1);

        float cn[PF];
        #pragma unroll
        for (int d = 0; d < PF; d++) {
            int j = j0 + d;
            if (j < ylen) {                      // uniform per block
                int jp = j + PF;
                cn[d] = (jp < ylen) ? base[(size_t)jp*TXn] : 0.f;

                float left = __shfl_up_sync(0xFFFFFFFFu, v, 1);
                if (lane == 0) left = (w == 0) ? NEGV : sb[(j & 1)*16 + (w - 1)];

                bool  di = v >= left;
                float nv = (di ? v : left) + c[d];
                if (x > j) nv = NEGV;

                unsigned bits = __ballot_sync(0xFFFFFFFFu, di) | force;
                if (lane == 0) dbase[(size_t)j*16] = bits;

                v = nv;
                if (lane == 31) sb[((j + 1) & 1)*16 + w] = nv;
                __syncthreads();
            }
        }
        #pragma unroll
        for (int d = 0; d < PF; d++) c[d] = cn[d];
    }
}

// -------------------- K4: backtrack + count (1 warp per batch, 32-bit words) ---
__global__ void __launch_bounds__(32)
bwd_kernel(const int* __restrict__ xl, const int* __restrict__ yl)
{
    int b = blockIdx.x, lane = threadIdx.x;
    int xlen = xl[b], ylen = yl[b];

    for (int j = ylen + lane; j < TYn; j += 32) g_xy[b*TYn + j] = 0;

    int idx = xlen - 1;
    for (int jhi = ylen - 1; jhi >= 0; jhi -= 32) {
        int steps = min(32, jhi + 1);
        int j = jhi - lane;
        int w0 = idx >> 5;                 // spans at most 2 words over 32 steps
        unsigned d0 = 0xFFFFFFFFu, d1 = 0xFFFFFFFFu;
        if (lane < steps) {
            const unsigned* p = g_dbits + ((size_t)b*TYn + j)*16;
            d0 = p[w0];
            if (w0 >= 1) d1 = p[w0-1];
        }
        int myidx = 0;
        for (int s = 0; s < steps; s++) {
            unsigned sel  = (w0 == (idx >> 5)) ? d0 : d1;
            unsigned word = __shfl_sync(0xFFFFFFFFu, sel, s);
            if (lane == s) myidx = idx;
            idx += (int)((word >> (idx & 31)) & 1u) - 1;
        }
        if (lane < steps) {
            g_xy[b*TYn + jhi - lane] = myidx;
            atomicAdd(&g_cnt[b*TXn + myidx], 1);
        }
    }
}

// -------------------- K5: y_mean / y_log_scale gathers -------------------------
__global__ void gather_kernel(const float* __restrict__ om,
                              const float* __restrict__ ols,
                              const int* __restrict__ yl,
                              float* __restrict__ out)
{
    int i = blockIdx.x * blockDim.x + threadIdx.x;
    if (i >= Bn*Cc*TYn) return;
    int b = i / (Cc*TYn);
    int r = i % (Cc*TYn);
    int c = r / TYn;
    int y = r % TYn;
    float m = 0.f, s = 0.f;
    if (y < yl[b]) {
        int x = g_xy[b*TYn + y];
        m = om [(size_t)(b*Cc + c)*TXn + x];
        s = ols[(size_t)(b*Cc + c)*TXn + x];
    }
    out[YMEAN_OFF + i] = m;
    out[YLOG_OFF  + i] = s;
}

// -------------------- K6: attn_out (zero + one-hot scatter) --------------------
__global__ void attn_kernel(const int* __restrict__ yl, float* __restrict__ out)
{
    int y = blockIdx.x, b = blockIdx.y, t = threadIdx.x;
    int xi = (y < yl[b]) ? g_xy[b*TYn + y] : -1;
    int x4 = t << 2;
    float4 r = make_float4(0.f, 0.f, 0.f, 0.f);
    if (xi >= x4 && xi < x4 + 4) ((float*)&r)[xi - x4] = 1.0f;
    *(float4*)&out[ATTN_OFF + ((size_t)b*TYn + y)*TXn + x4] = r;
}

// -------------------- K7: o_attn_dur --------------------------------------------
__global__ void dur_kernel(const int* __restrict__ xl, float* __restrict__ out)
{
    int i = blockIdx.x * blockDim.x + threadIdx.x;
    if (i >= Bn*TXn) return;
    int b = i / TXn, x = i % TXn;
    out[OADUR_OFF + i] = (x < xl[b]) ? log1pf((float)g_cnt[i]) : 0.f;
}

// -------------------- launch (single stream) -------------------------------------
extern "C" void kernel_launch(void* const* d_in, const int* in_sizes, int n_in,
                              void* d_out, int out_size)
{
    const float* om   = (const float*)d_in[0];
    const float* ols  = (const float*)d_in[1];
    const float* odur = (const float*)d_in[2];
    const float* z    = (const float*)d_in[3];
    const int*   xlen = (const int*)  d_in[4];
    const int*   ylen = (const int*)  d_in[5];
    float* out = (float*)d_out;

    prepx_kernel<<<(Bn*TXn + 255)/256, 256>>>(om, ols, odur, out);
    prepz_kernel<<<(Bn*Cc*TYn + 255)/256, 256>>>(z, ylen, out);
    fused_kernel<<<32 + NYT*Bn*4, 512>>>(xlen, ylen);   // 32 DP + 2048 gemm blocks
    bwd_kernel<<<Bn, 32>>>(xlen, ylen);
    gather_kernel<<<(Bn*Cc*TYn + 255)/256, 256>>>(om, ols, ylen, out);
    attn_kernel<<<dim3(TYn, Bn), 128>>>(ylen, out);
    dur_kernel<<<(Bn*TXn + 255)/256, 256>>>(xlen, out);
}

// round 13
// speedup vs baseline: 2.3834x; 1.0469x over previous
#include <cuda_runtime.h>
#include <cuda_bf16.h>
#include <math.h>
#include <stdint.h>

// Problem constants
#define Bn  32
#define Cc  80
#define TXn 512
#define TYn 2048
#define K2  160          // stacked K: [scale(80); mean*scale(80)]
#define NEGV (-1e9f)
#define LOG2PI 1.8378770664093453f
#define NYT (TYn/128)    // 16 y-tiles of 128 columns

// Output layout (flat f32, reference return order)
#define Z_OFF        0
#define YMEAN_OFF    (Bn*Cc*TYn)
#define YLOG_OFF     (2*Bn*Cc*TYn)
#define ATTN_OFF     (3*Bn*Cc*TYn)
#define ODUR_OFF     (ATTN_OFF + Bn*TYn*TXn)
#define OADUR_OFF    (ODUR_OFF + Bn*TXn)

// tail kernel block ranges (256 threads each)
#define TB_ATTN   (Bn*TYn/2)                  // 32768 blocks, 2 attn rows each
#define TB_GATH   (Bn*Cc*TYn/256)             // 20480 blocks
#define TB_DUR    (Bn*TXn/256)                // 64 blocks

// -------------------- scratch (__device__ globals) --------------------------
__device__ float    g_W[Bn*K2*TXn];              // [b][k][x]
__device__ float    g_Z[Bn*K2*TYn];              // [b][k][y]
__device__ float    g_rowA[Bn*TXn];              // logp1+logp4 per (b,x)
__device__ float    g_logpT[(size_t)Bn*TYn*TXn]; // 134 MB [b][y][x]
__device__ unsigned g_dbits[(size_t)Bn*TYn*16];  // dir bits, 32 per warp-word
__device__ int      g_xy[Bn*TYn];                // alignment index per (b,y)
__device__ int      g_cnt[Bn*TXn];               // per-x duration counts
__device__ int      g_prog[Bn*NYT];              // gemm tiles done per (b,ytile)

// -------------------- K1: per-(b,x) prep -------------------------------------
__global__ void prepx_kernel(const float* __restrict__ om,
                             const float* __restrict__ ols,
                             const float* __restrict__ odur,
                             float* __restrict__ out)
{
    int i = blockIdx.x * blockDim.x + threadIdx.x;
    if (i >= Bn*TXn) return;
    if (i < Bn*NYT) g_prog[i] = 0;     // reset producer counters each launch
    int b = i / TXn, x = i % TXn;
    const float* omb = om  + (size_t)b*Cc*TXn + x;
    const float* olb = ols + (size_t)b*Cc*TXn + x;
    float* wS = g_W + (size_t)b*K2*TXn + x;
    float sa = 0.f;
    #pragma unroll 4
    for (int c = 0; c < Cc; c++) {
        float l  = olb[(size_t)c*TXn];
        float sc = expf(-2.f*l);
        float m  = omb[(size_t)c*TXn];
        wS[(size_t)c*TXn]        = sc;
        wS[(size_t)(Cc+c)*TXn]   = m*sc;
        sa += -0.5f*LOG2PI - l - 0.5f*m*m*sc;
    }
    g_rowA[i] = sa;
    g_cnt[i]  = 0;
    out[ODUR_OFF + i] = odur[i];
}

// -------------------- K2: z masking + Z matrix --------------------------------
__global__ void prepz_kernel(const float* __restrict__ z,
                             const int* __restrict__ yl,
                             float* __restrict__ out)
{
    int i = blockIdx.x * blockDim.x + threadIdx.x;
    if (i >= Bn*Cc*TYn) return;
    int b = i / (Cc*TYn);
    int r = i % (Cc*TYn);
    int c = r / TYn;
    int y = r % TYn;
    float zv = z[i];
    if (y >= yl[b]) zv = 0.f;
    out[Z_OFF + i] = zv;
    size_t zb = (size_t)b*K2*TYn;
    g_Z[zb + (size_t)c*TYn + y]      = -0.5f*zv*zv;
    g_Z[zb + (size_t)(Cc+c)*TYn + y] = zv;
}

// -------------------- K3: fused gemm (producers) + forward DP (consumers) ------
// (verbatim from the passing R12 kernel)
__global__ void __launch_bounds__(512)
fused_kernel(const int* __restrict__ xl, const int* __restrict__ yl)
{
    __shared__ float smem[2*16*128];       // gemm tiles (fwd uses tiny slice)
    int tid = threadIdx.x;

    if (blockIdx.x >= 32) {
        // ---------------- GEMM producer role ----------------
        int gid = blockIdx.x - 32;
        int yt  = gid >> 7;                // 0..15 (slab-major)
        int rem = gid & 127;
        int b   = rem >> 2;
        int x0  = (rem & 3) * 128;
        int y0  = yt * 128;
        int xlen = xl[b], ylen = yl[b];

        bool skip = (x0 >= xlen) || (y0 >= ylen) ||
                    (x0 > y0 + 127) || (x0 + 127 < y0 - (ylen - xlen));
        if (!skip) {
            float (*zs)[128] = (float (*)[128])smem;
            float (*ws)[128] = (float (*)[128])(smem + 16*128);
            int lrow = tid >> 5;           // 0..15
            int lcol = (tid & 31) << 2;    // 0..124
            int ty   = tid >> 4;           // 0..31 (4 y each)
            int tx   = tid & 15;           // 0..15 (8 x each)

            const float* Zb = g_Z + (size_t)b*K2*TYn;
            const float* Wb = g_W + (size_t)b*K2*TXn;

            float acc[4][8] = {};
            for (int k0 = 0; k0 < K2; k0 += 16) {
                *(float4*)&zs[lrow][lcol] =
                    *(const float4*)&Zb[(size_t)(k0+lrow)*TYn + y0 + lcol];
                *(float4*)&ws[lrow][lcol] =
                    *(const float4*)&Wb[(size_t)(k0+lrow)*TXn + x0 + lcol];
                __syncthreads();
                #pragma unroll
                for (int k = 0; k < 16; k++) {
                    float4 zf = *(float4*)&zs[k][ty<<2];
                    float4 w0 = *(float4*)&ws[k][tx<<3];
                    float4 w1 = *(float4*)&ws[k][(tx<<3)+4];
                    float za[4] = {zf.x, zf.y, zf.z, zf.w};
                    float wa[8] = {w0.x,w0.y,w0.z,w0.w,w1.x,w1.y,w1.z,w1.w};
                    #pragma unroll
                    for (int i = 0; i < 4; i++)
                        #pragma unroll
                        for (int j = 0; j < 8; j++)
                            acc[i][j] += za[i]*wa[j];
                }
                __syncthreads();
            }

            float ra[8];
            #pragma unroll
            for (int j = 0; j < 8; j++)
                ra[j] = g_rowA[b*TXn + x0 + (tx<<3) + j];

            #pragma unroll
            for (int i = 0; i < 4; i++) {
                int y = y0 + (ty<<2) + i;
                float* op = g_logpT + ((size_t)b*TYn + y)*TXn + x0 + (tx<<3);
                float4 o0, o1;
                float* p0 = (float*)&o0; float* p1 = (float*)&o1;
                bool yok = (y < ylen);
                #pragma unroll
                for (int j = 0; j < 4; j++) {
                    int xa = x0 + (tx<<3) + j;
                    int xb = xa + 4;
                    p0[j] = (yok && xa < xlen) ? (acc[i][j]   + ra[j])   : 0.f;
                    p1[j] = (yok && xb < xlen) ? (acc[i][j+4] + ra[j+4]) : 0.f;
                }
                *(float4*)op       = o0;
                *(float4*)(op + 4) = o1;
            }
        }
        __threadfence();
        __syncthreads();
        if (tid == 0) atomicAdd(&g_prog[b*NYT + yt], 1);
        return;
    }

    // ---------------- forward-DP consumer role (R3 body + gating) ----------------
    int b    = blockIdx.x;
    int x    = tid;
    int w    = x >> 5, lane = x & 31;
    int xlen = xl[b], ylen = yl[b];

    float* sb = smem;                     // [2][16] boundary values

    unsigned force;
    {
        int rel = xlen - (w << 5);
        if (rel <= 0)      force = 0xFFFFFFFFu;
        else if (rel < 32) force = 0xFFFFFFFFu << rel;
        else               force = 0u;
    }

    float v = 0.f;
    if (lane == 31) { sb[0*16 + w] = 0.f; sb[1*16 + w] = 0.f; }

    const float* base  = g_logpT + (size_t)b*TYn*TXn + x;
    unsigned*    dbase = g_dbits + (size_t)b*TYn*16 + w;

    int last_yt = (ylen - 1) >> 7;

    auto gate = [&](int yt) {
        if (yt > last_yt) yt = last_yt;
        if (tid == 0) {
            const int* p = &g_prog[b*NYT + yt];
            int pv;
            do {
                asm volatile("ld.acquire.gpu.s32 %0, [%1];"
                             : "=r"(pv) : "l"(p) : "memory");
                if (pv < 4) __nanosleep(256);
            } while (pv < 4);
        }
        __syncthreads();
    };

    gate(0);

    const int PF = 8;
    float c[PF];
    #pragma unroll
    for (int d = 0; d < PF; d++)
        c[d] = (d < ylen) ? base[(size_t)d*TXn] : 0.f;
    __syncthreads();

    for (int j0 = 0; j0 < ylen; j0 += PF) {
        if ((j0 & 127) == 120) gate((j0 >> 7) + 1);

        float cn[PF];
        #pragma unroll
        for (int d = 0; d < PF; d++) {
            int j = j0 + d;
            if (j < ylen) {                      // uniform per block
                int jp = j + PF;
                cn[d] = (jp < ylen) ? base[(size_t)jp*TXn] : 0.f;

                float left = __shfl_up_sync(0xFFFFFFFFu, v, 1);
                if (lane == 0) left = (w == 0) ? NEGV : sb[(j & 1)*16 + (w - 1)];

                bool  di = v >= left;
                float nv = (di ? v : left) + c[d];
                if (x > j) nv = NEGV;

                unsigned bits = __ballot_sync(0xFFFFFFFFu, di) | force;
                if (lane == 0) dbase[(size_t)j*16] = bits;

                v = nv;
                if (lane == 31) sb[((j + 1) & 1)*16 + w] = nv;
                __syncthreads();
            }
        }
        #pragma unroll
        for (int d = 0; d < PF; d++) c[d] = cn[d];
    }
}

// -------------------- K4: backtrack + run-length counts ------------------------
// One warp per batch. Lanes preload candidate words per column; both candidates
// are broadcast per step (shfl operands are walk-independent -> pipeline ahead),
// the idx-dependent SELECT happens after. Lane 0 stores g_xy and run-length
// duration counts directly (path is monotone non-increasing: one run per x).
__global__ void __launch_bounds__(32)
bwd_kernel(const int* __restrict__ xl, const int* __restrict__ yl)
{
    int b = blockIdx.x, lane = threadIdx.x;
    int xlen = xl[b], ylen = yl[b];

    for (int j = ylen + lane; j < TYn; j += 32) g_xy[b*TYn + j] = 0;

    int idx = xlen - 1;
    int run = 0;
    for (int jhi = ylen - 1; jhi >= 0; jhi -= 32) {
        int steps = min(32, jhi + 1);
        int j = jhi - lane;
        int w0 = idx >> 5;                 // block-entry word; spans {w0, w0-1}
        unsigned d0 = 0xFFFFFFFFu, d1 = 0xFFFFFFFFu;
        if (lane < steps) {
            const unsigned* p = g_dbits + ((size_t)b*TYn + j)*16;
            d0 = p[w0];
            if (w0 >= 1) d1 = p[w0-1];
        }
        #pragma unroll 4
        for (int s = 0; s < steps; s++) {
            // walk-independent broadcasts (scheduler can issue ahead)
            unsigned e0 = __shfl_sync(0xFFFFFFFFu, d0, s);
            unsigned e1 = __shfl_sync(0xFFFFFFFFu, d1, s);
            unsigned word = ((idx >> 5) == w0) ? e0 : e1;
            unsigned bit  = (word >> (idx & 31)) & 1u;
            if (lane == 0) g_xy[b*TYn + jhi - s] = idx;
            run++;
            if (!bit) {
                if (lane == 0) g_cnt[b*TXn + idx] = run;
                run = 0;
            }
            idx += (int)bit - 1;
        }
    }
    if (run > 0 && lane == 0) g_cnt[b*TXn + idx] = run;
}

// -------------------- K5: merged tail (attn scatter + gathers + durations) -----
__global__ void __launch_bounds__(256)
tail_kernel(const float* __restrict__ om,
            const float* __restrict__ ols,
            const int* __restrict__ xlv,
            const int* __restrict__ ylv,
            float* __restrict__ out)
{
    int blk = blockIdx.x;
    int tid = threadIdx.x;

    if (blk < TB_ATTN) {
        // attn_out: 2 rows per block, 128 threads each, float4 stores
        int r = (blk << 1) + (tid >> 7);      // row id in [0, Bn*TYn)
        int b = r >> 11;                      // TYn = 2048
        int y = r & (TYn - 1);
        int t = tid & 127;
        int xi = (y < ylv[b]) ? g_xy[b*TYn + y] : -1;
        int x4 = t << 2;
        float4 v = make_float4(0.f, 0.f, 0.f, 0.f);
        if (xi >= x4 && xi < x4 + 4) ((float*)&v)[xi - x4] = 1.0f;
        *(float4*)&out[ATTN_OFF + (size_t)r*TXn + x4] = v;
    } else if (blk < TB_ATTN + TB_GATH) {
        // y_mean / y_log_scale gathers
        int i = (blk - TB_ATTN)*256 + tid;
        int b = i / (Cc*TYn);
        int r = i % (Cc*TYn);
        int c = r / TYn;
        int y = r % TYn;
        float m = 0.f, s = 0.f;
        if (y < ylv[b]) {
            int x = g_xy[b*TYn + y];
            m = om [(size_t)(b*Cc + c)*TXn + x];
            s = ols[(size_t)(b*Cc + c)*TXn + x];
        }
        out[YMEAN_OFF + i] = m;
        out[YLOG_OFF  + i] = s;
    } else {
        // o_attn_dur
        int i = (blk - TB_ATTN - TB_GATH)*256 + tid;
        int b = i / TXn, x = i % TXn;
        out[OADUR_OFF + i] = (x < xlv[b]) ? log1pf((float)g_cnt[i]) : 0.f;
    }
}

// -------------------- launch (single stream) -------------------------------------
extern "C" void kernel_launch(void* const* d_in, const int* in_sizes, int n_in,
                              void* d_out, int out_size)
{
    const float* om   = (const float*)d_in[0];
    const float* ols  = (const float*)d_in[1];
    const float* odur = (const float*)d_in[2];
    const float* z    = (const float*)d_in[3];
    const int*   xlen = (const int*)  d_in[4];
    const int*   ylen = (const int*)  d_in[5];
    float* out = (float*)d_out;

    prepx_kernel<<<(Bn*TXn + 255)/256, 256>>>(om, ols, odur, out);
    prepz_kernel<<<(Bn*Cc*TYn + 255)/256, 256>>>(z, ylen, out);
    fused_kernel<<<32 + NYT*Bn*4, 512>>>(xlen, ylen);   // 32 DP + 2048 gemm blocks
    bwd_kernel<<<Bn, 32>>>(xlen, ylen);
    tail_kernel<<<TB_ATTN + TB_GATH + TB_DUR, 256>>>(om, ols, xlen, ylen, out);
}